// round 10
// baseline (speedup 1.0000x reference)
#include <cuda_runtime.h>
#include <cuda_fp16.h>
#include <cstdint>
#include <cstddef>

// ---------------------------------------------------------------------------
// Problem constants
// ---------------------------------------------------------------------------
constexpr int B_ = 256;   // batches
constexpr int N_ = 1024;  // patches
constexpr int M_ = 128;   // words
constexpr int C_ = 512;   // channels (K)

constexpr int NTILE  = 256;          // patch tile (CTA N)
constexpr int NTILES = N_ / NTILE;   // 4
constexpr int KC     = 32;           // K chunk (fp32 elements)
constexpr int KCH    = C_ / KC;      // 16
constexpr int GTOT   = NTILES * KCH; // 64 chunks
constexpr int SPH    = 40;           // fp16 smem row stride in halfs (32 + 8 pad)

// fp32 staging for B (cp.async target): 256 rows x 128 B per stage, 3 stages
constexpr int B32ST_BYTES = 256 * 128;               // 32768
constexpr int NST32       = 3;

// fp16 operand buffers (ldmatrix source): A 128 x SPH + B 256 x SPH halfs, x2
constexpr int F16OFF    = NST32 * B32ST_BYTES;       // 98304
constexpr int F16_BYTES = (128 + 256) * SPH * 2;     // 30720 per buffer
constexpr int OFF_B16   = 128 * SPH * 2;             // 10240

// Float-indexed regions after stages + fp16 buffers (byte 159744)
constexpr int MASKF   = (F16OFF + 2 * F16_BYTES) / 4;  // 39936 (1024 floats)
constexpr int COLWF   = MASKF + 1024;                  // 4(wm) x 256 floats
constexpr int ROWREDF = COLWF + 1024;                  // 128 x 4(wn) floats
constexpr int REDF    = ROWREDF + 512;                 // 64 floats
constexpr int SMEM_BYTES = (REDF + 64) * 4;            // 170240 (~166 KB)

// ---------------------------------------------------------------------------
// Helpers
// ---------------------------------------------------------------------------
__device__ __forceinline__ uint32_t smem_u32(const void* p) {
    uint32_t a;
    asm("{ .reg .u64 t; cvta.to.shared.u64 t, %1; cvt.u32.u64 %0, t; }"
        : "=r"(a) : "l"(p));
    return a;
}

__device__ __forceinline__ void cp16(uint32_t dst, const void* src) {
    asm volatile("cp.async.cg.shared.global [%0], [%1], 16;"
                 :: "r"(dst), "l"(src) : "memory");
}
#define CP_COMMIT()  asm volatile("cp.async.commit_group;" ::: "memory")
#define CP_WAIT(n)   asm volatile("cp.async.wait_group %0;" :: "n"(n) : "memory")

__device__ __forceinline__ void ldm4(uint32_t* r, uint32_t addr) {
    asm volatile("ldmatrix.sync.aligned.m8n8.x4.shared.b16 {%0,%1,%2,%3}, [%4];"
                 : "=r"(r[0]), "=r"(r[1]), "=r"(r[2]), "=r"(r[3]) : "r"(addr));
}

// m16n8k16 row.col fp16 mma, fp32 accumulate (C==D)
__device__ __forceinline__ void mma16(float* c, const uint32_t* a,
                                      uint32_t b0, uint32_t b1) {
    asm volatile(
        "mma.sync.aligned.m16n8k16.row.col.f32.f16.f16.f32 "
        "{%0,%1,%2,%3}, {%4,%5,%6,%7}, {%8,%9}, {%0,%1,%2,%3};"
        : "+f"(c[0]), "+f"(c[1]), "+f"(c[2]), "+f"(c[3])
        : "r"(a[0]), "r"(a[1]), "r"(a[2]), "r"(a[3]), "r"(b0), "r"(b1));
}

// ---------------------------------------------------------------------------
// Kernel: one CTA per batch; 512 threads = 16 warps (4 M x 4 N).
// Warp tile m32 x n64. CTA tile 128(M) x 256(N). K chunked by 32 (2 x k16).
// B (patch): cp.async fp32 depth-3 staging -> smem fp16 convert (1 ahead).
// A (word):  L2-resident register staging (2 float4/thread) -> fp16 STS.
// ---------------------------------------------------------------------------
__global__ void __launch_bounds__(512, 1)
hrpa_kernel(const float* __restrict__ patch,   // (B, N, C)
            const float* __restrict__ word,    // (B, M, C)
            const float* __restrict__ mask,    // (B, N)
            float* __restrict__ out)           // (B, 1)
{
    extern __shared__ char smc[];
    float* fsm = reinterpret_cast<float*>(smc);
    const uint32_t smb = smem_u32(smc);

    const int tid  = threadIdx.x;
    const int lane = tid & 31;
    const int w    = tid >> 5;     // 0..15
    const int wm   = w & 3;        // M direction (rows wm*32 .. +31)
    const int wn   = w >> 2;       // N direction (cols wn*64 .. +63)
    const int g    = lane >> 2;    // quad group 0..7
    const int tig  = lane & 3;     // thread in group
    const int b    = blockIdx.x;

    // ldmatrix per-thread offsets (half units)
    const int mi = lane >> 3, r8 = lane & 7;
    const int aoff = (((mi & 1) << 3) + r8) * SPH + ((mi >> 1) << 3);
    const int boff = (((mi >> 1) << 3) + r8) * SPH + ((mi & 1) << 3);

    const float* wbase = word  + (size_t)b * M_ * C_;
    const float* pbase = patch + (size_t)b * N_ * C_;

    // loader/convert mapping: row = p*64 + (tid>>3), vec4 index = tid&7
    const int lr = tid >> 3;   // 0..63
    const int lv = tid & 7;

    // ---- mask -> smem, accumulate mask sum ----
    float masksum = 0.f;
    for (int i = tid; i < N_; i += 512) {
        float m = mask[b * N_ + i];
        fsm[MASKF + i] = m;
        masksum += m;
    }

    // cp.async B chunk (fp32) into stage gq%3; one commit group per chunk
    auto issue_cpB = [&](int gq) {
        const int s  = gq % NST32;
        const int nt = gq >> 4;
        const int k0 = (gq & 15) * KC;
        const uint32_t sb32 = smb + (uint32_t)(s * B32ST_BYTES);
        #pragma unroll
        for (int p = 0; p < 4; p++) {   // 256 rows
            const int r = p * 64 + lr;
            cp16(sb32 + (uint32_t)(r * 128 + lv * 16),
                 pbase + (size_t)(nt * NTILE + r) * C_ + k0 + lv * 4);
        }
        CP_COMMIT();
    };

    // smem fp32 B -> smem fp16 (ldmatrix layout) for chunk gq
    // (same thread reads its own cp.async slots: per-thread wait suffices)
    auto convertB = [&](int gq) {
        const char* src = smc + (gq % NST32) * B32ST_BYTES;
        char* dst = smc + F16OFF + (gq & 1) * F16_BYTES + OFF_B16;
        #pragma unroll
        for (int p = 0; p < 4; p++) {
            const int r = p * 64 + lr;
            float4 v = *(const float4*)(src + r * 128 + lv * 16);
            __half2 h0 = __floats2half2_rn(v.x, v.y);
            __half2 h1 = __floats2half2_rn(v.z, v.w);
            *(uint2*)(dst + (r * SPH + lv * 4) * 2) =
                make_uint2(*(uint32_t*)&h0, *(uint32_t*)&h1);
        }
    };

    // A (word): register-staged LDG (L2-resident after tile 0)
    auto loadA = [&](int gq, float4* sA) {
        const int k0 = (gq & 15) * KC;
        #pragma unroll
        for (int p = 0; p < 2; p++) {
            const int r = p * 64 + lr;
            sA[p] = *(const float4*)(wbase + (size_t)r * C_ + k0 + lv * 4);
        }
    };
    auto stsA = [&](int gq, const float4* sA) {
        char* dst = smc + F16OFF + (gq & 1) * F16_BYTES;
        #pragma unroll
        for (int p = 0; p < 2; p++) {
            const int r = p * 64 + lr;
            __half2 h0 = __floats2half2_rn(sA[p].x, sA[p].y);
            __half2 h1 = __floats2half2_rn(sA[p].z, sA[p].w);
            *(uint2*)(dst + (r * SPH + lv * 4) * 2) =
                make_uint2(*(uint32_t*)&h0, *(uint32_t*)&h1);
        }
    };

    float rmax[4] = {-3.0e38f, -3.0e38f, -3.0e38f, -3.0e38f};
    float colsum = 0.f;

    // ---- prologue: B stages 0..2 in flight; chunk 0 fp16 built ----
    issue_cpB(0); issue_cpB(1); issue_cpB(2);
    {
        float4 sA[2];
        loadA(0, sA);
        stsA(0, sA);
        CP_WAIT(2);        // own slots of B chunk 0 resident
        convertB(0);
    }
    __syncthreads();        // publish fp16 chunk 0

    for (int nt = 0; nt < NTILES; nt++) {
        float acc[2][8][4];
        #pragma unroll
        for (int mt = 0; mt < 2; mt++)
            #pragma unroll
            for (int j = 0; j < 8; j++)
                #pragma unroll
                for (int q = 0; q < 4; q++) acc[mt][j][q] = 0.f;

        for (int kc = 0; kc < KCH; kc++) {
            const int gq = nt * KCH + kc;
            const bool more = (gq + 1 < GTOT);

            // B fp32 chunk gq+1 resident (own slots) with chunk gq+2 in flight
            if (gq + 2 < GTOT) { CP_WAIT(1); } else { CP_WAIT(0); }
            // Publish fp16 chunk gq (built last iteration); retire readers of
            // fp32 stage gq%3 before issue_cpB(gq+3) reuses it.
            if (gq > 0) __syncthreads();

            if (gq + 3 < GTOT) issue_cpB(gq + 3);

            float4 sA[2];
            if (more) loadA(gq + 1, sA);       // L2 latency, covered below
            if (more) convertB(gq + 1);
            if (more) stsA(gq + 1, sA);

            // ---- MMAs on chunk gq from fp16 buffer gq&1 ----
            const uint32_t abase = smb + (uint32_t)(F16OFF + (gq & 1) * F16_BYTES);
            const uint32_t bbase = abase + OFF_B16;
            #pragma unroll
            for (int ks = 0; ks < 2; ks++) {
                uint32_t A0[4], A1[4];
                ldm4(A0, abase + (uint32_t)(((wm * 32     ) * SPH) + aoff + ks * 16) * 2);
                ldm4(A1, abase + (uint32_t)(((wm * 32 + 16) * SPH) + aoff + ks * 16) * 2);
                #pragma unroll
                for (int jj = 0; jj < 4; jj++) {
                    uint32_t Bf[4];
                    ldm4(Bf, bbase + (uint32_t)(((wn * 64 + jj * 16) * SPH) + boff + ks * 16) * 2);
                    mma16(acc[0][jj * 2    ], A0, Bf[0], Bf[1]);
                    mma16(acc[1][jj * 2    ], A1, Bf[0], Bf[1]);
                    mma16(acc[0][jj * 2 + 1], A0, Bf[2], Bf[3]);
                    mma16(acc[1][jj * 2 + 1], A1, Bf[2], Bf[3]);
                }
            }
        }
        __syncthreads();   // last chunk's fp16 consumers done; safe for epilogue reuse

        // ---- epilogue for this ntile ----
        // Thread owns rows {wm*32+mt*16+g, +8}, cols {wn*64+j*8+2tig, +1}.
        float colpart[16];
        #pragma unroll
        for (int j = 0; j < 8; j++) {
            #pragma unroll
            for (int cc = 0; cc < 2; cc++) {
                const int col = wn * 64 + j * 8 + 2 * tig + cc;
                const float pen = 1000.f * (1.f - fsm[MASKF + nt * NTILE + col]);
                float vmax = -3.0e38f;
                #pragma unroll
                for (int mt = 0; mt < 2; mt++) {
                    float v0 = acc[mt][j][cc];      // row m0+g
                    float v1 = acc[mt][j][cc + 2];  // row m0+8+g
                    v0 = v0 > 0.f ? v0 : 0.1f * v0;
                    v1 = v1 > 0.f ? v1 : 0.1f * v1;
                    rmax[mt * 2 + 0] = fmaxf(rmax[mt * 2 + 0], v0 - pen);
                    rmax[mt * 2 + 1] = fmaxf(rmax[mt * 2 + 1], v1 - pen);
                    vmax = fmaxf(vmax, fmaxf(v0, v1));
                }
                colpart[j * 2 + cc] = vmax;
            }
        }
        // column max across the 8 quad-groups (lanes differing in g)
        #pragma unroll
        for (int off = 4; off <= 16; off <<= 1)
            #pragma unroll
            for (int i = 0; i < 16; i++)
                colpart[i] = fmaxf(colpart[i], __shfl_xor_sync(0xffffffffu, colpart[i], off));
        if (g == 0) {
            #pragma unroll
            for (int j = 0; j < 8; j++)
                #pragma unroll
                for (int cc = 0; cc < 2; cc++)
                    fsm[COLWF + wm * NTILE + wn * 64 + j * 8 + 2 * tig + cc] =
                        colpart[j * 2 + cc];
        }
        __syncthreads();
        if (tid < NTILE) {
            const float cm = fmaxf(
                fmaxf(fsm[COLWF + tid],             fsm[COLWF + NTILE + tid]),
                fmaxf(fsm[COLWF + 2 * NTILE + tid], fsm[COLWF + 3 * NTILE + tid]));
            colsum += cm * fsm[MASKF + nt * NTILE + tid];
        }
        __syncthreads();
    }

    // ---- row-max combine (within quad, then across wn groups) ----
    #pragma unroll
    for (int off = 1; off <= 2; off <<= 1)
        #pragma unroll
        for (int i = 0; i < 4; i++)
            rmax[i] = fmaxf(rmax[i], __shfl_xor_sync(0xffffffffu, rmax[i], off));
    if (tig == 0) {
        #pragma unroll
        for (int mt = 0; mt < 2; mt++) {
            fsm[ROWREDF + (wm * 32 + mt * 16 +     g) * 4 + wn] = rmax[mt * 2 + 0];
            fsm[ROWREDF + (wm * 32 + mt * 16 + 8 + g) * 4 + wn] = rmax[mt * 2 + 1];
        }
    }
    __syncthreads();

    float rpart = 0.f;
    if (tid < 128) {
        rpart = fmaxf(fmaxf(fsm[ROWREDF + tid * 4 + 0], fsm[ROWREDF + tid * 4 + 1]),
                      fmaxf(fsm[ROWREDF + tid * 4 + 2], fsm[ROWREDF + tid * 4 + 3]));
    }

    // ---- block reduction of rpart / colsum / masksum ----
    #pragma unroll
    for (int off = 16; off > 0; off >>= 1) {
        rpart   += __shfl_down_sync(0xffffffffu, rpart,   off);
        colsum  += __shfl_down_sync(0xffffffffu, colsum,  off);
        masksum += __shfl_down_sync(0xffffffffu, masksum, off);
    }
    if (lane == 0) {
        fsm[REDF + w * 4 + 0] = rpart;
        fsm[REDF + w * 4 + 1] = colsum;
        fsm[REDF + w * 4 + 2] = masksum;
    }
    __syncthreads();
    if (tid == 0) {
        float rs = 0.f, cs = 0.f, ms = 0.f;
        #pragma unroll
        for (int i = 0; i < 16; i++) {
            rs += fsm[REDF + i * 4 + 0];
            cs += fsm[REDF + i * 4 + 1];
            ms += fsm[REDF + i * 4 + 2];
        }
        out[b] = rs * (1.f / 128.f) + cs / (ms + 1e-8f);
    }
}

// ---------------------------------------------------------------------------
// Host launch
// ---------------------------------------------------------------------------
extern "C" void kernel_launch(void* const* d_in, const int* in_sizes, int n_in,
                              void* d_out, int out_size)
{
    (void)in_sizes; (void)n_in; (void)out_size;
    const float* patch = (const float*)d_in[0];  // (B, N, C)
    const float* word  = (const float*)d_in[1];  // (B, M, C)
    const float* mask  = (const float*)d_in[2];  // (B, N)
    float* out = (float*)d_out;                  // (B, 1)

    cudaFuncSetAttribute(hrpa_kernel,
                         cudaFuncAttributeMaxDynamicSharedMemorySize, SMEM_BYTES);
    hrpa_kernel<<<B_, 512, SMEM_BYTES>>>(patch, word, mask, out);
}

// round 11
// speedup vs baseline: 1.5161x; 1.5161x over previous
#include <cuda_runtime.h>
#include <cuda_fp16.h>
#include <cstdint>
#include <cstddef>

// ---------------------------------------------------------------------------
// Problem constants
// ---------------------------------------------------------------------------
constexpr int B_ = 256;   // batches
constexpr int N_ = 1024;  // patches
constexpr int M_ = 128;   // words
constexpr int C_ = 512;   // channels (K)

constexpr int NTILE  = 256;          // patch tile (CTA N)
constexpr int NTILES = N_ / NTILE;   // 4
constexpr int KC     = 32;           // K chunk (fp32 elements)
constexpr int KCH    = C_ / KC;      // 16
constexpr int GTOT   = NTILES * KCH; // 64 chunks
constexpr int SPH    = 40;           // smem row stride in halfs (32 + 8 pad)

// Stage buffer geometry (bytes): A = 128x32 fp16, B = 256x32 fp16 (padded rows)
constexpr int A_SM_BYTES  = 128 * SPH * 2;           // 10240
constexpr int B_SM_BYTES  = 256 * SPH * 2;           // 20480
constexpr int STAGE_BYTES = A_SM_BYTES + B_SM_BYTES; // 30720
constexpr int OFF_Bt      = A_SM_BYTES;

// Float-indexed regions after the two stage buffers
constexpr int MASKF   = (2 * STAGE_BYTES) / 4;   // 15360 (1024 floats)
constexpr int COLWF   = MASKF + 1024;            // 4(wm) x 256 floats
constexpr int ROWREDF = COLWF + 1024;            // 128 x 4(wn) floats
constexpr int REDF    = ROWREDF + 512;           // 64 floats (16 warps x 4)
constexpr int SMEM_BYTES = (REDF + 64) * 4;      // 71936

// ---------------------------------------------------------------------------
// Helpers
// ---------------------------------------------------------------------------
__device__ __forceinline__ uint32_t smem_u32(const void* p) {
    uint32_t a;
    asm("{ .reg .u64 t; cvta.to.shared.u64 t, %1; cvt.u32.u64 %0, t; }"
        : "=r"(a) : "l"(p));
    return a;
}

__device__ __forceinline__ void ldm4(uint32_t* r, uint32_t addr) {
    asm volatile("ldmatrix.sync.aligned.m8n8.x4.shared.b16 {%0,%1,%2,%3}, [%4];"
                 : "=r"(r[0]), "=r"(r[1]), "=r"(r[2]), "=r"(r[3]) : "r"(addr));
}

// m16n8k16 row.col fp16 mma, fp32 accumulate (C==D)
__device__ __forceinline__ void mma16(float* c, const uint32_t* a,
                                      uint32_t b0, uint32_t b1) {
    asm volatile(
        "mma.sync.aligned.m16n8k16.row.col.f32.f16.f16.f32 "
        "{%0,%1,%2,%3}, {%4,%5,%6,%7}, {%8,%9}, {%0,%1,%2,%3};"
        : "+f"(c[0]), "+f"(c[1]), "+f"(c[2]), "+f"(c[3])
        : "r"(a[0]), "r"(a[1]), "r"(a[2]), "r"(a[3]), "r"(b0), "r"(b1));
}

// ---------------------------------------------------------------------------
// Kernel: one CTA per batch; 512 threads = 16 warps (4 M x 4 N).
// Warp tile m32 x n64. CTA tile 128(M) x 256(N). K chunked by 32 (2 x k16).
// Two-iteration register pipeline: registers carry chunk g+1 across the
// iteration boundary, so STS never stalls on LDG; LDG for g+2 has two full
// iterations of slack. Patch loads use .cs (streaming) so word stays in L2.
// ---------------------------------------------------------------------------
__global__ void __launch_bounds__(512, 1)
hrpa_kernel(const float* __restrict__ patch,   // (B, N, C)
            const float* __restrict__ word,    // (B, M, C)
            const float* __restrict__ mask,    // (B, N)
            float* __restrict__ out)           // (B, 1)
{
    extern __shared__ char smc[];
    float* fsm = reinterpret_cast<float*>(smc);
    const uint32_t smb = smem_u32(smc);

    const int tid  = threadIdx.x;
    const int lane = tid & 31;
    const int w    = tid >> 5;     // 0..15
    const int wm   = w & 3;        // M direction (rows wm*32 .. +31)
    const int wn   = w >> 2;       // N direction (cols wn*64 .. +63)
    const int g    = lane >> 2;    // quad group 0..7
    const int tig  = lane & 3;     // thread in group
    const int b    = blockIdx.x;

    // ldmatrix per-thread offsets (half units)
    const int mi = lane >> 3, r8 = lane & 7;
    const int aoff = (((mi & 1) << 3) + r8) * SPH + ((mi >> 1) << 3);
    const int boff = (((mi >> 1) << 3) + r8) * SPH + ((mi & 1) << 3);

    const float* wbase = word  + (size_t)b * M_ * C_;
    const float* pbase = patch + (size_t)b * N_ * C_;

    // loader mapping: slot row = p*64 + (tid>>3), vec4 index = tid&7
    const int lr = tid >> 3;   // 0..63
    const int lv = tid & 7;

    // ---- mask -> smem, accumulate mask sum ----
    float masksum = 0.f;
    for (int i = tid; i < N_; i += 512) {
        float m = mask[b * N_ + i];
        fsm[MASKF + i] = m;
        masksum += m;
    }

    auto load_regs = [&](int gq, float4* stA, float4* stB) {
        const int nt = gq >> 4;
        const int k0 = (gq & 15) * KC;
        #pragma unroll
        for (int p = 0; p < 2; p++) {   // A (word): L2-cacheable, reused x4
            const int r = p * 64 + lr;
            stA[p] = *(const float4*)(wbase + (size_t)r * C_ + k0 + lv * 4);
        }
        #pragma unroll
        for (int p = 0; p < 4; p++) {   // B (patch): streaming, read once
            const int r = p * 64 + lr;
            stB[p] = __ldcs((const float4*)(pbase + (size_t)(nt * NTILE + r) * C_ + k0 + lv * 4));
        }
    };
    auto sts_stage = [&](int buf, const float4* stA, const float4* stB) {
        char* base = smc + buf * STAGE_BYTES;
        #pragma unroll
        for (int p = 0; p < 2; p++) {
            const int r = p * 64 + lr;
            __half2 h0 = __floats2half2_rn(stA[p].x, stA[p].y);
            __half2 h1 = __floats2half2_rn(stA[p].z, stA[p].w);
            *(uint2*)(base + (r * SPH + lv * 4) * 2) =
                make_uint2(*(uint32_t*)&h0, *(uint32_t*)&h1);
        }
        #pragma unroll
        for (int p = 0; p < 4; p++) {
            const int r = p * 64 + lr;
            __half2 h0 = __floats2half2_rn(stB[p].x, stB[p].y);
            __half2 h1 = __floats2half2_rn(stB[p].z, stB[p].w);
            *(uint2*)(base + OFF_Bt + (r * SPH + lv * 4) * 2) =
                make_uint2(*(uint32_t*)&h0, *(uint32_t*)&h1);
        }
    };

    float rmax[4] = {-3.0e38f, -3.0e38f, -3.0e38f, -3.0e38f};
    float colsum = 0.f;

    // ---- prologue: chunk 0 -> buffer 0; chunk 1 held in registers ----
    float4 sA[2], sB[4];        // live across iterations (2-iter pipeline)
    load_regs(0, sA, sB);
    sts_stage(0, sA, sB);       // one-time LDG-latency stall
    load_regs(1, sA, sB);
    __syncthreads();

    for (int nt = 0; nt < NTILES; nt++) {
        float acc[2][8][4];
        #pragma unroll
        for (int mt = 0; mt < 2; mt++)
            #pragma unroll
            for (int j = 0; j < 8; j++)
                #pragma unroll
                for (int q = 0; q < 4; q++) acc[mt][j][q] = 0.f;

        for (int kc = 0; kc < KCH; kc++) {
            const int gq = nt * KCH + kc;

            // 1. STS chunk gq+1 from registers loaded LAST iteration
            //    (data arrived long ago -> no stall). Writes buffer (gq+1)&1,
            //    whose previous readers (mma(gq-1)) retired at the last barrier.
            if (gq + 1 < GTOT) sts_stage((gq + 1) & 1, sA, sB);

            // 2. Issue LDGs for chunk gq+2 (consumed next iteration).
            if (gq + 2 < GTOT) load_regs(gq + 2, sA, sB);

            // 3. MMAs on chunk gq from buffer gq&1 (published last barrier).
            const uint32_t abase = smb + (uint32_t)((gq & 1) * STAGE_BYTES);
            const uint32_t bbase = abase + OFF_Bt;
            #pragma unroll
            for (int ks = 0; ks < 2; ks++) {
                uint32_t A0[4], A1[4];
                ldm4(A0, abase + (uint32_t)(((wm * 32     ) * SPH) + aoff + ks * 16) * 2);
                ldm4(A1, abase + (uint32_t)(((wm * 32 + 16) * SPH) + aoff + ks * 16) * 2);
                #pragma unroll
                for (int jj = 0; jj < 4; jj++) {
                    uint32_t Bf[4];
                    ldm4(Bf, bbase + (uint32_t)(((wn * 64 + jj * 16) * SPH) + boff + ks * 16) * 2);
                    mma16(acc[0][jj * 2    ], A0, Bf[0], Bf[1]);
                    mma16(acc[1][jj * 2    ], A1, Bf[0], Bf[1]);
                    mma16(acc[0][jj * 2 + 1], A0, Bf[2], Bf[3]);
                    mma16(acc[1][jj * 2 + 1], A1, Bf[2], Bf[3]);
                }
            }

            // 4. Publish STS(gq+1); retire this chunk's buffer readers.
            __syncthreads();
        }

        // ---- epilogue for this ntile ----
        // Thread owns rows {wm*32+mt*16+g, +8}, cols {wn*64+j*8+2tig, +1}.
        float colpart[16];
        #pragma unroll
        for (int j = 0; j < 8; j++) {
            #pragma unroll
            for (int cc = 0; cc < 2; cc++) {
                const int col = wn * 64 + j * 8 + 2 * tig + cc;
                const float pen = 1000.f * (1.f - fsm[MASKF + nt * NTILE + col]);
                float vmax = -3.0e38f;
                #pragma unroll
                for (int mt = 0; mt < 2; mt++) {
                    float v0 = acc[mt][j][cc];      // row m0+g
                    float v1 = acc[mt][j][cc + 2];  // row m0+8+g
                    v0 = v0 > 0.f ? v0 : 0.1f * v0;
                    v1 = v1 > 0.f ? v1 : 0.1f * v1;
                    rmax[mt * 2 + 0] = fmaxf(rmax[mt * 2 + 0], v0 - pen);
                    rmax[mt * 2 + 1] = fmaxf(rmax[mt * 2 + 1], v1 - pen);
                    vmax = fmaxf(vmax, fmaxf(v0, v1));
                }
                colpart[j * 2 + cc] = vmax;
            }
        }
        // column max across the 8 quad-groups (lanes differing in g)
        #pragma unroll
        for (int off = 4; off <= 16; off <<= 1)
            #pragma unroll
            for (int i = 0; i < 16; i++)
                colpart[i] = fmaxf(colpart[i], __shfl_xor_sync(0xffffffffu, colpart[i], off));
        if (g == 0) {
            #pragma unroll
            for (int j = 0; j < 8; j++)
                #pragma unroll
                for (int cc = 0; cc < 2; cc++)
                    fsm[COLWF + wm * NTILE + wn * 64 + j * 8 + 2 * tig + cc] =
                        colpart[j * 2 + cc];
        }
        __syncthreads();
        if (tid < NTILE) {
            const float cm = fmaxf(
                fmaxf(fsm[COLWF + tid],             fsm[COLWF + NTILE + tid]),
                fmaxf(fsm[COLWF + 2 * NTILE + tid], fsm[COLWF + 3 * NTILE + tid]));
            colsum += cm * fsm[MASKF + nt * NTILE + tid];
        }
        __syncthreads();
    }

    // ---- row-max combine (within quad, then across wn groups) ----
    #pragma unroll
    for (int off = 1; off <= 2; off <<= 1)
        #pragma unroll
        for (int i = 0; i < 4; i++)
            rmax[i] = fmaxf(rmax[i], __shfl_xor_sync(0xffffffffu, rmax[i], off));
    if (tig == 0) {
        #pragma unroll
        for (int mt = 0; mt < 2; mt++) {
            fsm[ROWREDF + (wm * 32 + mt * 16 +     g) * 4 + wn] = rmax[mt * 2 + 0];
            fsm[ROWREDF + (wm * 32 + mt * 16 + 8 + g) * 4 + wn] = rmax[mt * 2 + 1];
        }
    }
    __syncthreads();

    float rpart = 0.f;
    if (tid < 128) {
        rpart = fmaxf(fmaxf(fsm[ROWREDF + tid * 4 + 0], fsm[ROWREDF + tid * 4 + 1]),
                      fmaxf(fsm[ROWREDF + tid * 4 + 2], fsm[ROWREDF + tid * 4 + 3]));
    }

    // ---- block reduction of rpart / colsum / masksum ----
    #pragma unroll
    for (int off = 16; off > 0; off >>= 1) {
        rpart   += __shfl_down_sync(0xffffffffu, rpart,   off);
        colsum  += __shfl_down_sync(0xffffffffu, colsum,  off);
        masksum += __shfl_down_sync(0xffffffffu, masksum, off);
    }
    if (lane == 0) {
        fsm[REDF + w * 4 + 0] = rpart;
        fsm[REDF + w * 4 + 1] = colsum;
        fsm[REDF + w * 4 + 2] = masksum;
    }
    __syncthreads();
    if (tid == 0) {
        float rs = 0.f, cs = 0.f, ms = 0.f;
        #pragma unroll
        for (int i = 0; i < 16; i++) {
            rs += fsm[REDF + i * 4 + 0];
            cs += fsm[REDF + i * 4 + 1];
            ms += fsm[REDF + i * 4 + 2];
        }
        out[b] = rs * (1.f / 128.f) + cs / (ms + 1e-8f);
    }
}

// ---------------------------------------------------------------------------
// Host launch
// ---------------------------------------------------------------------------
extern "C" void kernel_launch(void* const* d_in, const int* in_sizes, int n_in,
                              void* d_out, int out_size)
{
    (void)in_sizes; (void)n_in; (void)out_size;
    const float* patch = (const float*)d_in[0];  // (B, N, C)
    const float* word  = (const float*)d_in[1];  // (B, M, C)
    const float* mask  = (const float*)d_in[2];  // (B, N)
    float* out = (float*)d_out;                  // (B, 1)

    cudaFuncSetAttribute(hrpa_kernel,
                         cudaFuncAttributeMaxDynamicSharedMemorySize, SMEM_BYTES);
    hrpa_kernel<<<B_, 512, SMEM_BYTES>>>(patch, word, mask, out);
}